// round 5
// baseline (speedup 1.0000x reference)
#include <cuda_runtime.h>
#include <cstdint>

#define NB 2
#define NV 1024
#define NF 2048
#define NC 3
#define NH 128
#define NW 128
#define TS 16
#define TLX (NW / TS)      // 8 tiles in x
#define TLY (NH / TS)      // 8 tiles in y
#define CHK 512            // faces per scan chunk
#define NCHUNK (NF / CHK)  // 4

#define FTINY  ((float)1.1754943508222875e-35)            // finfo(f32).tiny * 1000
#define FINF   ((float)(3.4028234663852886e38 * 0.001))   // finfo(f32).max * 0.001
#define FLOWER ((float)(3.4028234663852886e38 * 0.0001))  // finfo(f32).max * 0.0001

// ---- exact-rounding helpers (match XLA's non-contracted mul/add) ----
__device__ __forceinline__ float f_mul(float a, float b) { return __fmul_rn(a, b); }
__device__ __forceinline__ float f_add(float a, float b) { return __fadd_rn(a, b); }
__device__ __forceinline__ float f_sub(float a, float b) { return __fsub_rn(a, b); }
__device__ __forceinline__ float plane3(float a, float x, float b, float y, float c) {
    return f_add(f_add(f_mul(a, x), f_mul(b, y)), c);
}

// Orderable key for fp32
__device__ __forceinline__ unsigned int fkey(float f) {
    unsigned int u = __float_as_uint(f);
    return (u & 0x80000000u) ? ~u : (u | 0x80000000u);
}
__device__ __forceinline__ float fkey_inv(unsigned int k) {
    unsigned int u = (k & 0x80000000u) ? (k ^ 0x80000000u) : ~k;
    return __uint_as_float(u);
}

__device__ __forceinline__ void bary_coeffs(
    float x0, float x1, float x2, float y0, float y1, float y2,
    float& l0x, float& l0y, float& l0c,
    float& l1x, float& l1y, float& l1c,
    float& l2x, float& l2y, float& l2c)
{
    float det = f_add(f_mul(f_sub(y1, y2), f_sub(x0, x2)),
                      f_mul(f_sub(x2, x1), f_sub(y0, y2)));
    float s  = (det > 0.0f) ? 1.0f : ((det < 0.0f) ? -1.0f : 0.0f);
    float dd = f_mul(s, fmaxf(fabsf(det), FTINY));
    float inv = __fdiv_rn(1.0f, dd);
    l0x = f_mul(f_sub(y1, y2), inv);
    l0y = f_mul(f_sub(x2, x1), inv);
    l0c = f_sub(f_mul(-l0x, x2), f_mul(l0y, y2));
    l1x = f_mul(f_sub(y2, y0), inv);
    l1y = f_mul(f_sub(x0, x2), inv);
    l1c = f_sub(f_mul(-l1x, x2), f_mul(l1y, y2));
    l2x = f_sub(-l0x, l1x);
    l2y = f_sub(-l0y, l1y);
    l2c = f_sub(f_sub(1.0f, l0c), l1c);
}

// Conservative: can plane (a,b,c) be >= 0 (after rounding) anywhere in the tile
// whose pixel centers span [cx-7.5, cx+7.5] x [cy-7.5, cy+7.5]?
// Upper bound = center value + 7.5*(|a|+|b|) + margin; margin >= 16x the 2^-24
// rounding bound of any pixel eval. NaN/inf coefficients never reject (safe).
__device__ __forceinline__ bool plane_may_pass(float a, float b, float c,
                                               float cx, float cy) {
    float ab = fabsf(a) + fabsf(b);
    float ub = plane3(a, cx, b, cy, c) + ab * 7.5f
             + (ab * 128.0f + fabsf(c)) * 1e-6f;
    return !(ub < 0.0f);
}

// ---- single fused kernel: setup + tile-reject + rasterize + shade ----
// Block = 256 threads = one 16x16 tile (1 pixel/thread). Grid = (8, 8, NB).
__global__ void __launch_bounds__(256) k_fused(
    const float* __restrict__ pt2d, const float* __restrict__ color,
    const float* __restrict__ pt3d, const float* __restrict__ normal,
    const float* __restrict__ Rm, const float* __restrict__ Tm,
    const int* __restrict__ face, float* __restrict__ out)
{
    __shared__ float  s_p2[3 * NV];                  // staged pt2d[b]  (12 KB)
    __shared__ float4 smA[CHK], smB[CHK], smC[CHK];  // survivors      (24 KB)
    __shared__ int    sidx[CHK];
    __shared__ int    scnt;

    int b    = blockIdx.z;
    int tid  = threadIdx.x;
    int lane = tid & 31;

    // stage pt2d for this batch (coalesced)
    const float4* p2g = (const float4*)(pt2d + b * 3 * NV);
    #pragma unroll
    for (int i = tid; i < 3 * NV / 4; i += 256)
        ((float4*)s_p2)[i] = p2g[i];
    __syncthreads();

    // camera offset o = R^T T (uniform per batch; identical ops in every thread)
    const float* R = Rm + b * 9;
    const float* T = Tm + b * 3;
    float o0 = f_add(f_add(f_mul(R[0], T[0]), f_mul(R[3], T[1])), f_mul(R[6], T[2]));
    float o1 = f_add(f_add(f_mul(R[1], T[0]), f_mul(R[4], T[1])), f_mul(R[7], T[2]));
    float o2 = f_add(f_add(f_mul(R[2], T[0]), f_mul(R[5], T[1])), f_mul(R[8], T[2]));

    int tx0 = blockIdx.x * TS, ty0 = blockIdx.y * TS;
    float cx = (float)tx0 + 7.5f, cy = (float)ty0 + 7.5f;
    int x = tx0 + (tid & 15);
    int y = ty0 + (tid >> 4);
    float xf = (float)x, yf = (float)y;

    const float* p3 = pt3d + b * 3 * NV;
    const float* nb = normal + b * 3 * NF;

    // init: depth = FINF, idx = 0 (matches reference argmin of all-INF buffer)
    unsigned long long best = ((unsigned long long)fkey(FINF)) << 32;

    for (int c = 0; c < NCHUNK; c++) {
        __syncthreads();                 // prev eval done before smem reuse
        if (tid == 0) scnt = 0;
        __syncthreads();

        // --- setup + tile-reject + compact (2 faces per thread) ---
        #pragma unroll
        for (int k = tid; k < CHK; k += 256) {
            int f = c * CHK + k;
            int i0 = face[f], i1 = face[NF + f], i2 = face[2 * NF + f];
            float x0 = s_p2[i0],          x1 = s_p2[i1],          x2 = s_p2[i2];
            float y0 = s_p2[NV + i0],     y1 = s_p2[NV + i1],     y2 = s_p2[NV + i2];
            float z0 = s_p2[2 * NV + i0], z1 = s_p2[2 * NV + i1], z2 = s_p2[2 * NV + i2];

            float v0x = p3[i0], v0y = p3[NV + i0], v0z = p3[2 * NV + i0];
            float nx = nb[f], ny = nb[NF + f], nz = nb[2 * NF + f];
            float dotv = f_add(f_add(f_mul(f_add(v0x, o0), nx),
                                     f_mul(f_add(v0y, o1), ny)),
                               f_mul(f_add(v0z, o2), nz));
            bool valid = (dotv < 0.0f) && (fminf(z0, fminf(z1, z2)) > 0.0f);

            float l0x, l0y, l0c, l1x, l1y, l1c, l2x, l2y, l2c;
            bary_coeffs(x0, x1, x2, y0, y1, y2,
                        l0x, l0y, l0c, l1x, l1y, l1c, l2x, l2y, l2c);

            bool keep = valid
                     && plane_may_pass(l0x, l0y, l0c, cx, cy)
                     && plane_may_pass(l1x, l1y, l1c, cx, cy)
                     && plane_may_pass(l2x, l2y, l2c, cx, cy);

            unsigned msk = __ballot_sync(0xFFFFFFFFu, keep);
            int wbase = 0;
            if (lane == 0 && msk) wbase = atomicAdd(&scnt, __popc(msk));
            wbase = __shfl_sync(0xFFFFFFFFu, wbase, 0);
            if (keep) {
                float Dx = f_add(f_add(f_mul(z0, l0x), f_mul(z1, l1x)), f_mul(z2, l2x));
                float Dy = f_add(f_add(f_mul(z0, l0y), f_mul(z1, l1y)), f_mul(z2, l2y));
                float Dc = f_add(f_add(f_mul(z0, l0c), f_mul(z1, l1c)), f_mul(z2, l2c));
                int p = wbase + __popc(msk & ((1u << lane) - 1u));
                sidx[p] = f;
                smA[p] = make_float4(l0x, l0y, l0c, l1x);
                smB[p] = make_float4(l1y, l1c, l2x, l2y);
                smC[p] = make_float4(l2c, Dx,  Dy,  Dc);
            }
        }
        __syncthreads();

        // --- eval survivors against this thread's pixel ---
        int m = scnt;
        for (int j = 0; j < m; j++) {
            float4 A  = smA[j];
            float4 Bq = smB[j];
            float4 Cq = smC[j];
            float l0 = plane3(A.x,  xf, A.y,  yf, A.z);
            float l1 = plane3(A.w,  xf, Bq.x, yf, Bq.y);
            float l2 = plane3(Bq.z, xf, Bq.w, yf, Cq.x);
            if (l0 >= 0.0f && l1 >= 0.0f && l2 >= 0.0f) {
                float d = plane3(Cq.y, xf, Cq.z, yf, Cq.w);
                if (d == d) {   // NaN never wins (matches where(isnan, INF))
                    unsigned long long kk =
                        (((unsigned long long)fkey(d)) << 32) | (unsigned)sidx[j];
                    best = min(best, kk);
                }
            }
        }
    }

    // --- shade (replicates _shade_one: recompute bary from winner's verts) ---
    int idx = (int)(best & 0xFFFFFFFFull);
    float depth = fkey_inv((unsigned int)(best >> 32));
    float mask = (depth < FLOWER) ? 1.0f : 0.0f;

    int i0 = face[idx], i1 = face[NF + idx], i2 = face[2 * NF + idx];
    float x0 = s_p2[i0],      x1 = s_p2[i1],      x2 = s_p2[i2];
    float y0 = s_p2[NV + i0], y1 = s_p2[NV + i1], y2 = s_p2[NV + i2];

    float l0x, l0y, l0c, l1x, l1y, l1c, l2x, l2y, l2c;
    bary_coeffs(x0, x1, x2, y0, y1, y2,
                l0x, l0y, l0c, l1x, l1y, l1c, l2x, l2y, l2c);

    const float* cb = color + b * 3 * NV;
    #pragma unroll
    for (int ch = 0; ch < NC; ch++) {
        float c0 = cb[ch * NV + i0], c1 = cb[ch * NV + i1], c2 = cb[ch * NV + i2];
        float Cx = f_add(f_add(f_mul(c0, l0x), f_mul(c1, l1x)), f_mul(c2, l2x));
        float Cy = f_add(f_add(f_mul(c0, l0y), f_mul(c1, l1y)), f_mul(c2, l2y));
        float Cc = f_add(f_add(f_mul(c0, l0c), f_mul(c1, l1c)), f_mul(c2, l2c));
        float val = f_add(f_add(f_mul(Cx, xf), f_mul(Cy, yf)), Cc);
        out[((b * NC + ch) * NH + y) * NW + x] = f_mul(mask, val);
    }
    out[NB * NC * NH * NW + (b * NH + y) * NW + x] = mask;
}

extern "C" void kernel_launch(void* const* d_in, const int* in_sizes, int n_in,
                              void* d_out, int out_size)
{
    const float* pt2d   = (const float*)d_in[0];
    const float* color  = (const float*)d_in[1];
    const float* pt3d   = (const float*)d_in[2];
    const float* normal = (const float*)d_in[3];
    const float* Rm     = (const float*)d_in[4];
    const float* Tm     = (const float*)d_in[5];
    const int*   face   = (const int*)d_in[6];
    float* out = (float*)d_out;

    dim3 grid(TLX, TLY, NB);
    k_fused<<<grid, 256>>>(pt2d, color, pt3d, normal, Rm, Tm, face, out);
}

// round 6
// speedup vs baseline: 2.0789x; 2.0789x over previous
#include <cuda_runtime.h>
#include <cstdint>

#define NB 2
#define NV 1024
#define NF 2048
#define NC 3
#define NH 128
#define NW 128
#define TS 16
#define TLX (NW / TS)      // 8 tiles in x
#define TLY (NH / TS)      // 8 tiles in y
#define NT  (TLX * TLY)    // 64 tiles per batch
#define SEG 8              // face-window split per tile
#define WIN (NF / SEG)     // 256 faces per window

#define FTINY  ((float)1.1754943508222875e-35)            // finfo(f32).tiny * 1000
#define FINF   ((float)(3.4028234663852886e38 * 0.001))   // finfo(f32).max * 0.001
#define FLOWER ((float)(3.4028234663852886e38 * 0.0001))  // finfo(f32).max * 0.0001

// Scratch (no allocations allowed)
__device__ float4 g_face[NB * NF * 3];                // plane records: A,B,C
__device__ float g_shade[NB * NF * 12];               // per-channel (Cx,Cy,Cc)
__device__ unsigned long long g_scr[NB * NH * NW];    // packed (depthKey, faceIdx)
__device__ unsigned int g_tick[NB * NT];              // per-tile completion tickets

// ---- exact-rounding helpers (match XLA's non-contracted mul/add) ----
__device__ __forceinline__ float f_mul(float a, float b) { return __fmul_rn(a, b); }
__device__ __forceinline__ float f_add(float a, float b) { return __fadd_rn(a, b); }
__device__ __forceinline__ float f_sub(float a, float b) { return __fsub_rn(a, b); }
__device__ __forceinline__ float plane3(float a, float x, float b, float y, float c) {
    return f_add(f_add(f_mul(a, x), f_mul(b, y)), c);
}

// Orderable key for fp32
__device__ __forceinline__ unsigned int fkey(float f) {
    unsigned int u = __float_as_uint(f);
    return (u & 0x80000000u) ? ~u : (u | 0x80000000u);
}
__device__ __forceinline__ float fkey_inv(unsigned int k) {
    unsigned int u = (k & 0x80000000u) ? (k ^ 0x80000000u) : ~k;
    return __uint_as_float(u);
}

__device__ __forceinline__ void bary_coeffs(
    float x0, float x1, float x2, float y0, float y1, float y2,
    float& l0x, float& l0y, float& l0c,
    float& l1x, float& l1y, float& l1c,
    float& l2x, float& l2y, float& l2c)
{
    float det = f_add(f_mul(f_sub(y1, y2), f_sub(x0, x2)),
                      f_mul(f_sub(x2, x1), f_sub(y0, y2)));
    float s  = (det > 0.0f) ? 1.0f : ((det < 0.0f) ? -1.0f : 0.0f);
    float dd = f_mul(s, fmaxf(fabsf(det), FTINY));
    float inv = __fdiv_rn(1.0f, dd);
    l0x = f_mul(f_sub(y1, y2), inv);
    l0y = f_mul(f_sub(x2, x1), inv);
    l0c = f_sub(f_mul(-l0x, x2), f_mul(l0y, y2));
    l1x = f_mul(f_sub(y2, y0), inv);
    l1y = f_mul(f_sub(x0, x2), inv);
    l1c = f_sub(f_mul(-l1x, x2), f_mul(l1y, y2));
    l2x = f_sub(-l0x, l1x);
    l2y = f_sub(-l0y, l1y);
    l2c = f_sub(f_sub(1.0f, l0c), l1c);
}

// Conservative: can plane (a,b,c) be >= 0 (after rounding) anywhere in the tile
// whose pixel centers span [cx-7.5, cx+7.5] x [cy-7.5, cy+7.5]?
__device__ __forceinline__ bool plane_may_pass(float a, float b, float c,
                                               float cx, float cy) {
    float ab = fabsf(a) + fabsf(b);
    float ub = plane3(a, cx, b, cy, c) + ab * 7.5f
             + (ab * 128.0f + fabsf(c)) * 1e-6f;
    return !(ub < 0.0f);
}

// ---- K1: init keys/tickets (blocks 0..127) + per-face setup (blocks 128..143) ----
#define SCR_BLOCKS ((NB * NH * NW) / 256)          // 128
#define SETUP_BLOCKS ((NB * NF) / 256)             // 16
__global__ void k_setup(const float* __restrict__ pt2d, const float* __restrict__ pt3d,
                        const float* __restrict__ normal, const float* __restrict__ Rm,
                        const float* __restrict__ Tm, const int* __restrict__ face,
                        const float* __restrict__ color)
{
    if (blockIdx.x < SCR_BLOCKS) {
        int id = blockIdx.x * 256 + threadIdx.x;
        g_scr[id] = ((unsigned long long)fkey(FINF)) << 32;  // idx = 0
        if (blockIdx.x == 0 && threadIdx.x < NB * NT)
            g_tick[threadIdx.x] = 0u;
        return;
    }
    int id = (blockIdx.x - SCR_BLOCKS) * 256 + threadIdx.x;
    if (id >= NB * NF) return;
    int b = id / NF, f = id % NF;

    int i0 = face[f], i1 = face[NF + f], i2 = face[2 * NF + f];
    const float* p2 = pt2d + b * 3 * NV;
    float x0 = p2[i0],          x1 = p2[i1],          x2 = p2[i2];
    float y0 = p2[NV + i0],     y1 = p2[NV + i1],     y2 = p2[NV + i2];
    float z0 = p2[2 * NV + i0], z1 = p2[2 * NV + i1], z2 = p2[2 * NV + i2];

    // norm cull: ((v0 + R^T T) . n) < 0
    const float* p3 = pt3d + b * 3 * NV;
    float v0x = p3[i0], v0y = p3[NV + i0], v0z = p3[2 * NV + i0];
    const float* nb = normal + b * 3 * NF;
    float nx = nb[f], ny = nb[NF + f], nz = nb[2 * NF + f];
    const float* R = Rm + b * 9;
    const float* T = Tm + b * 3;
    float o0 = f_add(f_add(f_mul(R[0], T[0]), f_mul(R[3], T[1])), f_mul(R[6], T[2]));
    float o1 = f_add(f_add(f_mul(R[1], T[0]), f_mul(R[4], T[1])), f_mul(R[7], T[2]));
    float o2 = f_add(f_add(f_mul(R[2], T[0]), f_mul(R[5], T[1])), f_mul(R[8], T[2]));
    float dotv = f_add(f_add(f_mul(f_add(v0x, o0), nx),
                             f_mul(f_add(v0y, o1), ny)),
                       f_mul(f_add(v0z, o2), nz));
    bool valid = (dotv < 0.0f) && (fminf(z0, fminf(z1, z2)) > 0.0f);

    float l0x, l0y, l0c, l1x, l1y, l1c, l2x, l2y, l2c;
    bary_coeffs(x0, x1, x2, y0, y1, y2, l0x, l0y, l0c, l1x, l1y, l1c, l2x, l2y, l2c);

    float Dx = f_add(f_add(f_mul(z0, l0x), f_mul(z1, l1x)), f_mul(z2, l2x));
    float Dy = f_add(f_add(f_mul(z0, l0y), f_mul(z1, l1y)), f_mul(z2, l2y));
    float Dc = f_add(f_add(f_mul(z0, l0c), f_mul(z1, l1c)), f_mul(z2, l2c));

    // shading planes (bitwise-identical to reference recomputation at shade time)
    const float* cb = color + b * 3 * NV;
    float sh[12];
    #pragma unroll
    for (int ch = 0; ch < NC; ch++) {
        float c0 = cb[ch * NV + i0], c1 = cb[ch * NV + i1], c2 = cb[ch * NV + i2];
        sh[ch * 3 + 0] = f_add(f_add(f_mul(c0, l0x), f_mul(c1, l1x)), f_mul(c2, l2x));
        sh[ch * 3 + 1] = f_add(f_add(f_mul(c0, l0y), f_mul(c1, l1y)), f_mul(c2, l2y));
        sh[ch * 3 + 2] = f_add(f_add(f_mul(c0, l0c), f_mul(c1, l1c)), f_mul(c2, l2c));
    }
    float4* s4 = (float4*)(g_shade + id * 12);
    s4[0] = make_float4(sh[0], sh[1], sh[2], sh[3]);
    s4[1] = make_float4(sh[4], sh[5], sh[6], sh[7]);
    s4[2] = make_float4(sh[8], sh[9], sh[10], sh[11]);

    // fold validity: invalid -> plane0 = (0,0,-1): tile-rejected & uncoverable
    if (!valid) { l0x = 0.0f; l0y = 0.0f; l0c = -1.0f; }
    g_face[id * 3 + 0] = make_float4(l0x, l0y, l0c, l1x);
    g_face[id * 3 + 1] = make_float4(l1y, l1c, l2x, l2y);
    g_face[id * 3 + 2] = make_float4(l2c, Dx,  Dy,  Dc);
}

// ---- K2: raster (scan -> reject -> compact -> eval) + last-block shade ----
// Block = 128 threads = one 16x16 tile, 2 px/thread (rows y, y+8).
__global__ void __launch_bounds__(128) k_raster(float* __restrict__ out) {
    __shared__ float4 smA[WIN], smB[WIN], smC[WIN];   // 12 KB
    __shared__ int    sidx[WIN];
    __shared__ int    scnt;
    __shared__ unsigned int s_tick;

    int b   = blockIdx.z / SEG;
    int seg = blockIdx.z % SEG;
    int tid = threadIdx.x;
    int lane = tid & 31;

    int tile = blockIdx.y * TLX + blockIdx.x;
    int tx0 = blockIdx.x * TS, ty0 = blockIdx.y * TS;
    float cx = (float)tx0 + 7.5f, cy = (float)ty0 + 7.5f;

    if (tid == 0) scnt = 0;
    __syncthreads();

    // scan + compact: 2 faces per thread
    int base = seg * WIN;
    #pragma unroll
    for (int k = tid; k < WIN; k += 128) {
        int f = base + k;
        const float4* fp = &g_face[(b * NF + f) * 3];
        float4 A  = fp[0];
        float4 Bq = fp[1];
        float4 Cq = fp[2];
        bool keep = plane_may_pass(A.x,  A.y,  A.z,  cx, cy)
                 && plane_may_pass(A.w,  Bq.x, Bq.y, cx, cy)
                 && plane_may_pass(Bq.z, Bq.w, Cq.x, cx, cy);
        unsigned mask = __ballot_sync(0xFFFFFFFFu, keep);
        int wbase = 0;
        if (lane == 0 && mask) wbase = atomicAdd(&scnt, __popc(mask));
        wbase = __shfl_sync(0xFFFFFFFFu, wbase, 0);
        if (keep) {
            int p = wbase + __popc(mask & ((1u << lane) - 1u));
            sidx[p] = f;
            smA[p] = A; smB[p] = Bq; smC[p] = Cq;
        }
    }
    __syncthreads();
    int m = scnt;

    int x  = tx0 + (tid & 15);
    int y0 = ty0 + (tid >> 4);          // rows 0..7 of tile
    float xf  = (float)x;
    float yf0 = (float)y0;
    float yf1 = (float)(y0 + 8);

    const unsigned long long INIT = 0xFFFFFFFFFFFFFFFFull;
    unsigned long long best0 = INIT, best1 = INIT;

    for (int j = 0; j < m; j++) {
        float4 A  = smA[j];
        float4 Bq = smB[j];
        float4 Cq = smC[j];
        unsigned long long fi = (unsigned long long)(unsigned)sidx[j];

        {   // pixel (x, y0)
            float l0 = plane3(A.x,  xf, A.y,  yf0, A.z);
            float l1 = plane3(A.w,  xf, Bq.x, yf0, Bq.y);
            float l2 = plane3(Bq.z, xf, Bq.w, yf0, Cq.x);
            if (l0 >= 0.0f && l1 >= 0.0f && l2 >= 0.0f) {
                float d = plane3(Cq.y, xf, Cq.z, yf0, Cq.w);
                if (d == d) {   // NaN never wins (matches where(isnan, INF))
                    unsigned long long k = (((unsigned long long)fkey(d)) << 32) | fi;
                    best0 = min(best0, k);
                }
            }
        }
        {   // pixel (x, y0+8)
            float l0 = plane3(A.x,  xf, A.y,  yf1, A.z);
            float l1 = plane3(A.w,  xf, Bq.x, yf1, Bq.y);
            float l2 = plane3(Bq.z, xf, Bq.w, yf1, Cq.x);
            if (l0 >= 0.0f && l1 >= 0.0f && l2 >= 0.0f) {
                float d = plane3(Cq.y, xf, Cq.z, yf1, Cq.w);
                if (d == d) {
                    unsigned long long k = (((unsigned long long)fkey(d)) << 32) | fi;
                    best1 = min(best1, k);
                }
            }
        }
    }

    int pix0 = b * NH * NW + y0 * NW + x;
    int pix1 = pix0 + 8 * NW;
    if (best0 != INIT) atomicMin(&g_scr[pix0], best0);
    if (best1 != INIT) atomicMin(&g_scr[pix1], best1);

    // ---- publication + ticket: last block for this tile shades it ----
    __threadfence();                        // atomicMins visible before ticket
    __syncthreads();                        // whole block published
    if (tid == 0) s_tick = atomicAdd(&g_tick[b * NT + tile], 1u);
    __syncthreads();
    if (s_tick != SEG - 1) return;

    // this is the last block: all 8 segments' results are fenced + complete
    #pragma unroll
    for (int h = 0; h < 2; h++) {
        int pix = h ? pix1 : pix0;
        int yy  = h ? (y0 + 8) : y0;
        unsigned long long key = *(volatile unsigned long long*)&g_scr[pix];
        int idx = (int)(key & 0xFFFFFFFFull);
        float depth = fkey_inv((unsigned int)(key >> 32));
        float mk = (depth < FLOWER) ? 1.0f : 0.0f;

        const float4* sp = (const float4*)(g_shade + (b * NF + idx) * 12);
        float4 s0 = sp[0];
        float4 s1 = sp[1];
        float4 s2 = sp[2];

        float yfl = (float)yy;
        float v0 = f_add(f_add(f_mul(s0.x, xf), f_mul(s0.y, yfl)), s0.z);
        float v1 = f_add(f_add(f_mul(s0.w, xf), f_mul(s1.x, yfl)), s1.y);
        float v2 = f_add(f_add(f_mul(s1.z, xf), f_mul(s1.w, yfl)), s2.x);

        out[((b * NC + 0) * NH + yy) * NW + x] = f_mul(mk, v0);
        out[((b * NC + 1) * NH + yy) * NW + x] = f_mul(mk, v1);
        out[((b * NC + 2) * NH + yy) * NW + x] = f_mul(mk, v2);
        out[NB * NC * NH * NW + (b * NH + yy) * NW + x] = mk;
    }
}

extern "C" void kernel_launch(void* const* d_in, const int* in_sizes, int n_in,
                              void* d_out, int out_size)
{
    const float* pt2d   = (const float*)d_in[0];
    const float* color  = (const float*)d_in[1];
    const float* pt3d   = (const float*)d_in[2];
    const float* normal = (const float*)d_in[3];
    const float* Rm     = (const float*)d_in[4];
    const float* Tm     = (const float*)d_in[5];
    const int*   face   = (const int*)d_in[6];
    float* out = (float*)d_out;

    k_setup<<<SCR_BLOCKS + SETUP_BLOCKS, 256>>>(pt2d, pt3d, normal, Rm, Tm, face, color);
    dim3 g2(TLX, TLY, NB * SEG);
    k_raster<<<g2, 128>>>(out);
}

// round 7
// speedup vs baseline: 2.2789x; 1.0962x over previous
#include <cuda_runtime.h>
#include <cstdint>

#define NB 2
#define NV 1024
#define NF 2048
#define NC 3
#define NH 128
#define NW 128
#define TS 16
#define TLX (NW / TS)      // 8 tiles in x
#define TLY (NH / TS)      // 8 tiles in y
#define NT  (TLX * TLY)    // 64 tiles per batch
#define SEG 16             // face-window split per tile
#define WIN (NF / SEG)     // 128 faces per window

#define FTINY  ((float)1.1754943508222875e-35)            // finfo(f32).tiny * 1000
#define FINF   ((float)(3.4028234663852886e38 * 0.001))   // finfo(f32).max * 0.001
#define FLOWER ((float)(3.4028234663852886e38 * 0.0001))  // finfo(f32).max * 0.0001

// Scratch (no allocations allowed)
__device__ float4 g_face[NB * NF * 3];                // plane records: A,B,C
__device__ float g_shade[NB * NF * 12];               // per-channel (Cx,Cy,Cc)
__device__ unsigned long long g_scr[NB * NH * NW];    // packed (depthKey, faceIdx)
__device__ unsigned int g_tick[NB * NT];              // per-tile completion tickets

// ---- exact-rounding helpers (match XLA's non-contracted mul/add) ----
__device__ __forceinline__ float f_mul(float a, float b) { return __fmul_rn(a, b); }
__device__ __forceinline__ float f_add(float a, float b) { return __fadd_rn(a, b); }
__device__ __forceinline__ float f_sub(float a, float b) { return __fsub_rn(a, b); }
__device__ __forceinline__ float plane3(float a, float x, float b, float y, float c) {
    return f_add(f_add(f_mul(a, x), f_mul(b, y)), c);
}

// Orderable key for fp32
__device__ __forceinline__ unsigned int fkey(float f) {
    unsigned int u = __float_as_uint(f);
    return (u & 0x80000000u) ? ~u : (u | 0x80000000u);
}
__device__ __forceinline__ float fkey_inv(unsigned int k) {
    unsigned int u = (k & 0x80000000u) ? (k ^ 0x80000000u) : ~k;
    return __uint_as_float(u);
}

__device__ __forceinline__ void bary_coeffs(
    float x0, float x1, float x2, float y0, float y1, float y2,
    float& l0x, float& l0y, float& l0c,
    float& l1x, float& l1y, float& l1c,
    float& l2x, float& l2y, float& l2c)
{
    float det = f_add(f_mul(f_sub(y1, y2), f_sub(x0, x2)),
                      f_mul(f_sub(x2, x1), f_sub(y0, y2)));
    float s  = (det > 0.0f) ? 1.0f : ((det < 0.0f) ? -1.0f : 0.0f);
    float dd = f_mul(s, fmaxf(fabsf(det), FTINY));
    float inv = __fdiv_rn(1.0f, dd);
    l0x = f_mul(f_sub(y1, y2), inv);
    l0y = f_mul(f_sub(x2, x1), inv);
    l0c = f_sub(f_mul(-l0x, x2), f_mul(l0y, y2));
    l1x = f_mul(f_sub(y2, y0), inv);
    l1y = f_mul(f_sub(x0, x2), inv);
    l1c = f_sub(f_mul(-l1x, x2), f_mul(l1y, y2));
    l2x = f_sub(-l0x, l1x);
    l2y = f_sub(-l0y, l1y);
    l2c = f_sub(f_sub(1.0f, l0c), l1c);
}

// Per-plane, per-quadrant conservative pass test (halfspan 3.5 around quadrant
// center). margin >= 16x the 2^-24 rounding bound of any pixel eval.
// NaN/inf coefficients never reject (comparison false -> keep). Returns 4-bit
// mask of quadrants where plane may be >= 0; caller ANDs across planes.
__device__ __forceinline__ unsigned quad_mask(float a, float b, float c,
                                              float tx, float ty) {
    float ab  = fabsf(a) + fabsf(b);
    float off = ab * 3.5f + (ab * 128.0f + fabsf(c)) * 1e-6f;
    unsigned m = 0;
    #pragma unroll
    for (int q = 0; q < 4; q++) {
        float cxq = tx + (float)((q & 1) * 8) + 3.5f;
        float cyq = ty + (float)((q >> 1) * 8) + 3.5f;
        float ub = plane3(a, cxq, b, cyq, c) + off;
        if (!(ub < 0.0f)) m |= (1u << q);
    }
    return m;
}

// ---- K1: init keys/tickets (blocks 0..127) + per-face setup (blocks 128..143) ----
#define SCR_BLOCKS ((NB * NH * NW) / 256)          // 128
#define SETUP_BLOCKS ((NB * NF) / 256)             // 16
__global__ void k_setup(const float* __restrict__ pt2d, const float* __restrict__ pt3d,
                        const float* __restrict__ normal, const float* __restrict__ Rm,
                        const float* __restrict__ Tm, const int* __restrict__ face,
                        const float* __restrict__ color)
{
    if (blockIdx.x < SCR_BLOCKS) {
        int id = blockIdx.x * 256 + threadIdx.x;
        g_scr[id] = ((unsigned long long)fkey(FINF)) << 32;  // idx = 0
        if (blockIdx.x == 0 && threadIdx.x < NB * NT)
            g_tick[threadIdx.x] = 0u;
        return;
    }
    int id = (blockIdx.x - SCR_BLOCKS) * 256 + threadIdx.x;
    if (id >= NB * NF) return;
    int b = id / NF, f = id % NF;

    int i0 = face[f], i1 = face[NF + f], i2 = face[2 * NF + f];
    const float* p2 = pt2d + b * 3 * NV;
    float x0 = p2[i0],          x1 = p2[i1],          x2 = p2[i2];
    float y0 = p2[NV + i0],     y1 = p2[NV + i1],     y2 = p2[NV + i2];
    float z0 = p2[2 * NV + i0], z1 = p2[2 * NV + i1], z2 = p2[2 * NV + i2];

    // norm cull: ((v0 + R^T T) . n) < 0
    const float* p3 = pt3d + b * 3 * NV;
    float v0x = p3[i0], v0y = p3[NV + i0], v0z = p3[2 * NV + i0];
    const float* nb = normal + b * 3 * NF;
    float nx = nb[f], ny = nb[NF + f], nz = nb[2 * NF + f];
    const float* R = Rm + b * 9;
    const float* T = Tm + b * 3;
    float o0 = f_add(f_add(f_mul(R[0], T[0]), f_mul(R[3], T[1])), f_mul(R[6], T[2]));
    float o1 = f_add(f_add(f_mul(R[1], T[0]), f_mul(R[4], T[1])), f_mul(R[7], T[2]));
    float o2 = f_add(f_add(f_mul(R[2], T[0]), f_mul(R[5], T[1])), f_mul(R[8], T[2]));
    float dotv = f_add(f_add(f_mul(f_add(v0x, o0), nx),
                             f_mul(f_add(v0y, o1), ny)),
                       f_mul(f_add(v0z, o2), nz));
    bool valid = (dotv < 0.0f) && (fminf(z0, fminf(z1, z2)) > 0.0f);

    float l0x, l0y, l0c, l1x, l1y, l1c, l2x, l2y, l2c;
    bary_coeffs(x0, x1, x2, y0, y1, y2, l0x, l0y, l0c, l1x, l1y, l1c, l2x, l2y, l2c);

    float Dx = f_add(f_add(f_mul(z0, l0x), f_mul(z1, l1x)), f_mul(z2, l2x));
    float Dy = f_add(f_add(f_mul(z0, l0y), f_mul(z1, l1y)), f_mul(z2, l2y));
    float Dc = f_add(f_add(f_mul(z0, l0c), f_mul(z1, l1c)), f_mul(z2, l2c));

    // shading planes (bitwise-identical to reference recomputation at shade time)
    const float* cb = color + b * 3 * NV;
    float sh[12];
    #pragma unroll
    for (int ch = 0; ch < NC; ch++) {
        float c0 = cb[ch * NV + i0], c1 = cb[ch * NV + i1], c2 = cb[ch * NV + i2];
        sh[ch * 3 + 0] = f_add(f_add(f_mul(c0, l0x), f_mul(c1, l1x)), f_mul(c2, l2x));
        sh[ch * 3 + 1] = f_add(f_add(f_mul(c0, l0y), f_mul(c1, l1y)), f_mul(c2, l2y));
        sh[ch * 3 + 2] = f_add(f_add(f_mul(c0, l0c), f_mul(c1, l1c)), f_mul(c2, l2c));
    }
    float4* s4 = (float4*)(g_shade + id * 12);
    s4[0] = make_float4(sh[0], sh[1], sh[2], sh[3]);
    s4[1] = make_float4(sh[4], sh[5], sh[6], sh[7]);
    s4[2] = make_float4(sh[8], sh[9], sh[10], sh[11]);

    // fold validity: invalid -> plane0 = (0,0,-1): rejected everywhere & uncoverable
    if (!valid) { l0x = 0.0f; l0y = 0.0f; l0c = -1.0f; }
    g_face[id * 3 + 0] = make_float4(l0x, l0y, l0c, l1x);
    g_face[id * 3 + 1] = make_float4(l1y, l1c, l2x, l2y);
    g_face[id * 3 + 2] = make_float4(l2c, Dx,  Dy,  Dc);
}

// ---- K2: raster (scan -> quadrant reject -> compact -> eval) + last-block shade ----
// Block = 128 threads = one 16x16 tile. Warp w owns 8x8 quadrant (w&1, w>>1);
// lane l -> pixel (qx*8 + (l&7), qy*8 + (l>>3)) and the one 4 rows below.
__global__ void __launch_bounds__(128) k_raster(float* __restrict__ out) {
    __shared__ float4 smA[WIN], smB[WIN], smC[WIN];   // 6 KB
    __shared__ int    sidx[WIN];                      // faceIdx | (quadMask<<16)
    __shared__ int    scnt;
    __shared__ unsigned int s_tick;

    int b   = blockIdx.z / SEG;
    int seg = blockIdx.z % SEG;
    int tid = threadIdx.x;
    int w    = tid >> 5;
    int lane = tid & 31;

    int tile = blockIdx.y * TLX + blockIdx.x;
    int tx0 = blockIdx.x * TS, ty0 = blockIdx.y * TS;
    float txf = (float)tx0, tyf = (float)ty0;

    if (tid == 0) scnt = 0;
    __syncthreads();

    // scan + compact: exactly 1 face per thread (WIN == blockDim)
    {
        int f = seg * WIN + tid;
        const float4* fp = &g_face[(b * NF + f) * 3];
        float4 A  = fp[0];
        float4 Bq = fp[1];
        float4 Cq = fp[2];
        unsigned qm = quad_mask(A.x,  A.y,  A.z,  txf, tyf)
                    & quad_mask(A.w,  Bq.x, Bq.y, txf, tyf)
                    & quad_mask(Bq.z, Bq.w, Cq.x, txf, tyf);
        bool keep = (qm != 0u);
        unsigned mask = __ballot_sync(0xFFFFFFFFu, keep);
        int wbase = 0;
        if (lane == 0 && mask) wbase = atomicAdd(&scnt, __popc(mask));
        wbase = __shfl_sync(0xFFFFFFFFu, wbase, 0);
        if (keep) {
            int p = wbase + __popc(mask & ((1u << lane) - 1u));
            sidx[p] = f | (int)(qm << 16);
            smA[p] = A; smB[p] = Bq; smC[p] = Cq;
        }
    }
    __syncthreads();
    int m = scnt;

    int x  = tx0 + (w & 1) * 8 + (lane & 7);
    int y0 = ty0 + (w >> 1) * 8 + (lane >> 3);   // rows 0..3 of quadrant
    float xf  = (float)x;
    float yf0 = (float)y0;
    float yf1 = (float)(y0 + 4);

    const unsigned long long INIT = 0xFFFFFFFFFFFFFFFFull;
    unsigned long long best0 = INIT, best1 = INIT;
    unsigned qbit = 1u << (16 + w);

    for (int j = 0; j < m; j++) {
        int e = sidx[j];
        if (!((unsigned)e & qbit)) continue;     // warp-uniform skip
        float4 A  = smA[j];
        float4 Bq = smB[j];
        float4 Cq = smC[j];
        unsigned long long fi = (unsigned long long)(unsigned)(e & 0xFFFF);

        {   // pixel (x, y0)
            float l0 = plane3(A.x,  xf, A.y,  yf0, A.z);
            float l1 = plane3(A.w,  xf, Bq.x, yf0, Bq.y);
            float l2 = plane3(Bq.z, xf, Bq.w, yf0, Cq.x);
            if (l0 >= 0.0f && l1 >= 0.0f && l2 >= 0.0f) {
                float d = plane3(Cq.y, xf, Cq.z, yf0, Cq.w);
                if (d == d) {   // NaN never wins (matches where(isnan, INF))
                    unsigned long long k = (((unsigned long long)fkey(d)) << 32) | fi;
                    best0 = min(best0, k);
                }
            }
        }
        {   // pixel (x, y0+4)
            float l0 = plane3(A.x,  xf, A.y,  yf1, A.z);
            float l1 = plane3(A.w,  xf, Bq.x, yf1, Bq.y);
            float l2 = plane3(Bq.z, xf, Bq.w, yf1, Cq.x);
            if (l0 >= 0.0f && l1 >= 0.0f && l2 >= 0.0f) {
                float d = plane3(Cq.y, xf, Cq.z, yf1, Cq.w);
                if (d == d) {
                    unsigned long long k = (((unsigned long long)fkey(d)) << 32) | fi;
                    best1 = min(best1, k);
                }
            }
        }
    }

    int pix0 = b * NH * NW + y0 * NW + x;
    int pix1 = pix0 + 4 * NW;
    if (best0 != INIT) atomicMin(&g_scr[pix0], best0);
    if (best1 != INIT) atomicMin(&g_scr[pix1], best1);

    // ---- publication + ticket: last block for this tile shades it ----
    __threadfence();                        // atomicMins visible before ticket
    __syncthreads();                        // whole block published
    if (tid == 0) s_tick = atomicAdd(&g_tick[b * NT + tile], 1u);
    __syncthreads();
    if (s_tick != SEG - 1) return;

    // last block: all segments' results are fenced + complete
    #pragma unroll
    for (int h = 0; h < 2; h++) {
        int pix = h ? pix1 : pix0;
        int yy  = h ? (y0 + 4) : y0;
        unsigned long long key = *(volatile unsigned long long*)&g_scr[pix];
        int idx = (int)(key & 0xFFFFFFFFull);
        float depth = fkey_inv((unsigned int)(key >> 32));
        float mk = (depth < FLOWER) ? 1.0f : 0.0f;

        const float4* sp = (const float4*)(g_shade + (b * NF + idx) * 12);
        float4 s0 = sp[0];
        float4 s1 = sp[1];
        float4 s2 = sp[2];

        float yfl = (float)yy;
        float v0 = f_add(f_add(f_mul(s0.x, xf), f_mul(s0.y, yfl)), s0.z);
        float v1 = f_add(f_add(f_mul(s0.w, xf), f_mul(s1.x, yfl)), s1.y);
        float v2 = f_add(f_add(f_mul(s1.z, xf), f_mul(s1.w, yfl)), s2.x);

        out[((b * NC + 0) * NH + yy) * NW + x] = f_mul(mk, v0);
        out[((b * NC + 1) * NH + yy) * NW + x] = f_mul(mk, v1);
        out[((b * NC + 2) * NH + yy) * NW + x] = f_mul(mk, v2);
        out[NB * NC * NH * NW + (b * NH + yy) * NW + x] = mk;
    }
}

extern "C" void kernel_launch(void* const* d_in, const int* in_sizes, int n_in,
                              void* d_out, int out_size)
{
    const float* pt2d   = (const float*)d_in[0];
    const float* color  = (const float*)d_in[1];
    const float* pt3d   = (const float*)d_in[2];
    const float* normal = (const float*)d_in[3];
    const float* Rm     = (const float*)d_in[4];
    const float* Tm     = (const float*)d_in[5];
    const int*   face   = (const int*)d_in[6];
    float* out = (float*)d_out;

    k_setup<<<SCR_BLOCKS + SETUP_BLOCKS, 256>>>(pt2d, pt3d, normal, Rm, Tm, face, color);
    dim3 g2(TLX, TLY, NB * SEG);
    k_raster<<<g2, 128>>>(out);
}

// round 8
// speedup vs baseline: 2.3177x; 1.0170x over previous
#include <cuda_runtime.h>
#include <cstdint>

#define NB 2
#define NV 1024
#define NF 2048
#define NC 3
#define NH 128
#define NW 128
#define TS 16
#define TLX (NW / TS)      // 8 tiles in x
#define TLY (NH / TS)      // 8 tiles in y
#define NT  (TLX * TLY)    // 64 tiles per batch
#define SEG 16             // face-window split per tile
#define WIN (NF / SEG)     // 128 faces per window == blockDim

#define FTINY  ((float)1.1754943508222875e-35)            // finfo(f32).tiny * 1000
#define FINF   ((float)(3.4028234663852886e38 * 0.001))   // finfo(f32).max * 0.001
#define FLOWER ((float)(3.4028234663852886e38 * 0.0001))  // finfo(f32).max * 0.0001

// Persistent scratch. Zero-initialized at module load; the kernel restores the
// all-zero state before exiting, so every graph replay sees a clean slate.
__device__ unsigned long long g_scr[NB * NH * NW];    // ~packed(depthKey,faceIdx); 0 = empty
__device__ unsigned int g_tick[NB * NT];              // per-tile completion tickets

// ---- exact-rounding helpers (match XLA's non-contracted mul/add) ----
__device__ __forceinline__ float f_mul(float a, float b) { return __fmul_rn(a, b); }
__device__ __forceinline__ float f_add(float a, float b) { return __fadd_rn(a, b); }
__device__ __forceinline__ float f_sub(float a, float b) { return __fsub_rn(a, b); }
__device__ __forceinline__ float plane3(float a, float x, float b, float y, float c) {
    return f_add(f_add(f_mul(a, x), f_mul(b, y)), c);
}

// Orderable key for fp32
__device__ __forceinline__ unsigned int fkey(float f) {
    unsigned int u = __float_as_uint(f);
    return (u & 0x80000000u) ? ~u : (u | 0x80000000u);
}
__device__ __forceinline__ float fkey_inv(unsigned int k) {
    unsigned int u = (k & 0x80000000u) ? (k ^ 0x80000000u) : ~k;
    return __uint_as_float(u);
}

__device__ __forceinline__ void bary_coeffs(
    float x0, float x1, float x2, float y0, float y1, float y2,
    float& l0x, float& l0y, float& l0c,
    float& l1x, float& l1y, float& l1c,
    float& l2x, float& l2y, float& l2c)
{
    float det = f_add(f_mul(f_sub(y1, y2), f_sub(x0, x2)),
                      f_mul(f_sub(x2, x1), f_sub(y0, y2)));
    float s  = (det > 0.0f) ? 1.0f : ((det < 0.0f) ? -1.0f : 0.0f);
    float dd = f_mul(s, fmaxf(fabsf(det), FTINY));
    float inv = __fdiv_rn(1.0f, dd);
    l0x = f_mul(f_sub(y1, y2), inv);
    l0y = f_mul(f_sub(x2, x1), inv);
    l0c = f_sub(f_mul(-l0x, x2), f_mul(l0y, y2));
    l1x = f_mul(f_sub(y2, y0), inv);
    l1y = f_mul(f_sub(x0, x2), inv);
    l1c = f_sub(f_mul(-l1x, x2), f_mul(l1y, y2));
    l2x = f_sub(-l0x, l1x);
    l2y = f_sub(-l0y, l1y);
    l2c = f_sub(f_sub(1.0f, l0c), l1c);
}

// Per-plane, per-quadrant conservative pass test (halfspan 3.5 around quadrant
// center). margin >= 16x the 2^-24 rounding bound of any pixel eval.
// NaN/inf coefficients never reject (comparison false -> keep).
__device__ __forceinline__ unsigned quad_mask(float a, float b, float c,
                                              float tx, float ty) {
    float ab  = fabsf(a) + fabsf(b);
    float off = ab * 3.5f + (ab * 128.0f + fabsf(c)) * 1e-6f;
    unsigned m = 0;
    #pragma unroll
    for (int q = 0; q < 4; q++) {
        float cxq = tx + (float)((q & 1) * 8) + 3.5f;
        float cyq = ty + (float)((q >> 1) * 8) + 3.5f;
        float ub = plane3(a, cxq, b, cyq, c) + off;
        if (!(ub < 0.0f)) m |= (1u << q);
    }
    return m;
}

// ---- single kernel: inline setup + quadrant reject + eval + last-block shade ----
// Block = 128 threads = one 16x16 tile. Warp w owns the 8x8 quadrant (w&1, w>>1);
// lane l -> pixel (qx*8+(l&7), qy*8+(l>>3)) and the one 4 rows below.
__global__ void __launch_bounds__(128) k_all(
    const float* __restrict__ pt2d, const float* __restrict__ color,
    const float* __restrict__ pt3d, const float* __restrict__ normal,
    const float* __restrict__ Rm, const float* __restrict__ Tm,
    const int* __restrict__ face, float* __restrict__ out)
{
    __shared__ float4 smA[WIN], smB[WIN], smC[WIN];   // 6 KB survivors
    __shared__ int    sidx[WIN];                      // faceIdx | (quadMask<<16)
    __shared__ int    scnt;
    __shared__ unsigned int s_tick;

    int b   = blockIdx.z / SEG;
    int seg = blockIdx.z % SEG;
    int tid = threadIdx.x;
    int w    = tid >> 5;
    int lane = tid & 31;

    int tile = blockIdx.y * TLX + blockIdx.x;
    int tx0 = blockIdx.x * TS, ty0 = blockIdx.y * TS;
    float txf = (float)tx0, tyf = (float)ty0;

    if (tid == 0) scnt = 0;
    __syncthreads();

    const float* p2 = pt2d + b * 3 * NV;
    const float* p3 = pt3d + b * 3 * NV;
    const float* nbp = normal + b * 3 * NF;
    const float* R = Rm + b * 9;
    const float* T = Tm + b * 3;

    // ---- inline setup + tile reject + compact: 1 face per thread ----
    {
        int f = seg * WIN + tid;
        int i0 = __ldg(&face[f]), i1 = __ldg(&face[NF + f]), i2 = __ldg(&face[2 * NF + f]);
        float x0 = __ldg(&p2[i0]),          x1 = __ldg(&p2[i1]),          x2 = __ldg(&p2[i2]);
        float y0 = __ldg(&p2[NV + i0]),     y1 = __ldg(&p2[NV + i1]),     y2 = __ldg(&p2[NV + i2]);
        float z0 = __ldg(&p2[2 * NV + i0]), z1 = __ldg(&p2[2 * NV + i1]), z2 = __ldg(&p2[2 * NV + i2]);

        // norm cull: ((v0 + R^T T) . n) < 0
        float v0x = __ldg(&p3[i0]), v0y = __ldg(&p3[NV + i0]), v0z = __ldg(&p3[2 * NV + i0]);
        float nx = __ldg(&nbp[f]), ny = __ldg(&nbp[NF + f]), nz = __ldg(&nbp[2 * NF + f]);
        float o0 = f_add(f_add(f_mul(R[0], T[0]), f_mul(R[3], T[1])), f_mul(R[6], T[2]));
        float o1 = f_add(f_add(f_mul(R[1], T[0]), f_mul(R[4], T[1])), f_mul(R[7], T[2]));
        float o2 = f_add(f_add(f_mul(R[2], T[0]), f_mul(R[5], T[1])), f_mul(R[8], T[2]));
        float dotv = f_add(f_add(f_mul(f_add(v0x, o0), nx),
                                 f_mul(f_add(v0y, o1), ny)),
                           f_mul(f_add(v0z, o2), nz));
        bool valid = (dotv < 0.0f) && (fminf(z0, fminf(z1, z2)) > 0.0f);

        float l0x, l0y, l0c, l1x, l1y, l1c, l2x, l2y, l2c;
        bary_coeffs(x0, x1, x2, y0, y1, y2, l0x, l0y, l0c, l1x, l1y, l1c, l2x, l2y, l2c);

        unsigned qm = 0u;
        if (valid) {
            qm = quad_mask(l0x, l0y, l0c, txf, tyf)
               & quad_mask(l1x, l1y, l1c, txf, tyf)
               & quad_mask(l2x, l2y, l2c, txf, tyf);
        }
        bool keep = (qm != 0u);
        unsigned mask = __ballot_sync(0xFFFFFFFFu, keep);
        int wbase = 0;
        if (lane == 0 && mask) wbase = atomicAdd(&scnt, __popc(mask));
        wbase = __shfl_sync(0xFFFFFFFFu, wbase, 0);
        if (keep) {
            float Dx = f_add(f_add(f_mul(z0, l0x), f_mul(z1, l1x)), f_mul(z2, l2x));
            float Dy = f_add(f_add(f_mul(z0, l0y), f_mul(z1, l1y)), f_mul(z2, l2y));
            float Dc = f_add(f_add(f_mul(z0, l0c), f_mul(z1, l1c)), f_mul(z2, l2c));
            int p = wbase + __popc(mask & ((1u << lane) - 1u));
            sidx[p] = f | (int)(qm << 16);
            smA[p] = make_float4(l0x, l0y, l0c, l1x);
            smB[p] = make_float4(l1y, l1c, l2x, l2y);
            smC[p] = make_float4(l2c, Dx,  Dy,  Dc);
        }
    }
    __syncthreads();
    int m = scnt;

    int x  = tx0 + (w & 1) * 8 + (lane & 7);
    int y0 = ty0 + (w >> 1) * 8 + (lane >> 3);   // rows 0..3 of quadrant
    float xf  = (float)x;
    float yf0 = (float)y0;
    float yf1 = (float)(y0 + 4);

    // seed = (FINF, idx 0): replicates reference argmin over all-INF buffer,
    // including the corner where a covered depth >= FINF loses to "empty".
    const unsigned long long KEY0 = ((unsigned long long)fkey(FINF)) << 32;
    unsigned long long best0 = KEY0, best1 = KEY0;
    unsigned qbit = 1u << (16 + w);

    for (int j = 0; j < m; j++) {
        int e = sidx[j];
        if (!((unsigned)e & qbit)) continue;     // warp-uniform skip
        float4 A  = smA[j];
        float4 Bq = smB[j];
        float4 Cq = smC[j];
        unsigned long long fi = (unsigned long long)(unsigned)(e & 0xFFFF);

        {   // pixel (x, y0)
            float l0 = plane3(A.x,  xf, A.y,  yf0, A.z);
            float l1 = plane3(A.w,  xf, Bq.x, yf0, Bq.y);
            float l2 = plane3(Bq.z, xf, Bq.w, yf0, Cq.x);
            if (l0 >= 0.0f && l1 >= 0.0f && l2 >= 0.0f) {
                float d = plane3(Cq.y, xf, Cq.z, yf0, Cq.w);
                if (d == d) {   // NaN never wins (matches where(isnan, INF))
                    unsigned long long k = (((unsigned long long)fkey(d)) << 32) | fi;
                    best0 = min(best0, k);
                }
            }
        }
        {   // pixel (x, y0+4)
            float l0 = plane3(A.x,  xf, A.y,  yf1, A.z);
            float l1 = plane3(A.w,  xf, Bq.x, yf1, Bq.y);
            float l2 = plane3(Bq.z, xf, Bq.w, yf1, Cq.x);
            if (l0 >= 0.0f && l1 >= 0.0f && l2 >= 0.0f) {
                float d = plane3(Cq.y, xf, Cq.z, yf1, Cq.w);
                if (d == d) {
                    unsigned long long k = (((unsigned long long)fkey(d)) << 32) | fi;
                    best1 = min(best1, k);
                }
            }
        }
    }

    // publish: min over key == max over ~key; 0 is the neutral "empty" element,
    // so the zero-initialized (and self-cleaned) g_scr needs no init pass.
    int pix0 = b * NH * NW + y0 * NW + x;
    int pix1 = pix0 + 4 * NW;
    if (best0 != KEY0) atomicMax(&g_scr[pix0], ~best0);
    if (best1 != KEY0) atomicMax(&g_scr[pix1], ~best1);

    // ---- publication + ticket: last block for this tile shades it ----
    __threadfence();                        // atomics visible before ticket
    __syncthreads();                        // whole block published
    if (tid == 0) s_tick = atomicAdd(&g_tick[b * NT + tile], 1u);
    __syncthreads();
    if (s_tick != SEG - 1) return;

    // last block: all segments' results are fenced + complete
    const float* cb = color + b * 3 * NV;
    #pragma unroll
    for (int h = 0; h < 2; h++) {
        int pix = h ? pix1 : pix0;
        int yy  = h ? (y0 + 4) : y0;
        unsigned long long s = *(volatile unsigned long long*)&g_scr[pix];
        *(volatile unsigned long long*)&g_scr[pix] = 0ull;   // self-clean for next replay
        unsigned long long key = (s == 0ull) ? KEY0 : ~s;
        int idx = (int)(key & 0xFFFFFFFFull);
        float depth = fkey_inv((unsigned int)(key >> 32));
        float mk = (depth < FLOWER) ? 1.0f : 0.0f;

        // replicate _shade_one: recompute bary from winner's verts + colors
        int i0 = __ldg(&face[idx]), i1 = __ldg(&face[NF + idx]), i2 = __ldg(&face[2 * NF + idx]);
        float x0 = __ldg(&p2[i0]),      x1 = __ldg(&p2[i1]),      x2 = __ldg(&p2[i2]);
        float ya = __ldg(&p2[NV + i0]), yb = __ldg(&p2[NV + i1]), yc = __ldg(&p2[NV + i2]);

        float l0x, l0y, l0c, l1x, l1y, l1c, l2x, l2y, l2c;
        bary_coeffs(x0, x1, x2, ya, yb, yc, l0x, l0y, l0c, l1x, l1y, l1c, l2x, l2y, l2c);

        float yfl = (float)yy;
        #pragma unroll
        for (int ch = 0; ch < NC; ch++) {
            float c0 = __ldg(&cb[ch * NV + i0]);
            float c1 = __ldg(&cb[ch * NV + i1]);
            float c2 = __ldg(&cb[ch * NV + i2]);
            float Cx = f_add(f_add(f_mul(c0, l0x), f_mul(c1, l1x)), f_mul(c2, l2x));
            float Cy = f_add(f_add(f_mul(c0, l0y), f_mul(c1, l1y)), f_mul(c2, l2y));
            float Cc = f_add(f_add(f_mul(c0, l0c), f_mul(c1, l1c)), f_mul(c2, l2c));
            float val = f_add(f_add(f_mul(Cx, xf), f_mul(Cy, yfl)), Cc);
            out[((b * NC + ch) * NH + yy) * NW + x] = f_mul(mk, val);
        }
        out[NB * NC * NH * NW + (b * NH + yy) * NW + x] = mk;
    }
    if (tid == 0) g_tick[b * NT + tile] = 0u;   // self-clean ticket
}

extern "C" void kernel_launch(void* const* d_in, const int* in_sizes, int n_in,
                              void* d_out, int out_size)
{
    const float* pt2d   = (const float*)d_in[0];
    const float* color  = (const float*)d_in[1];
    const float* pt3d   = (const float*)d_in[2];
    const float* normal = (const float*)d_in[3];
    const float* Rm     = (const float*)d_in[4];
    const float* Tm     = (const float*)d_in[5];
    const int*   face   = (const int*)d_in[6];
    float* out = (float*)d_out;

    dim3 grid(TLX, TLY, NB * SEG);
    k_all<<<grid, 128>>>(pt2d, color, pt3d, normal, Rm, Tm, face, out);
}